// round 13
// baseline (speedup 1.0000x reference)
#include <cuda_runtime.h>
#include <cuda_fp16.h>
#include <cstdint>
#include <cstddef>

// ---------------------------------------------------------------------------
// Portable PTX helpers (base sm_103 target: no 'a'-suffix instructions)
// ---------------------------------------------------------------------------
__device__ __forceinline__ uint32_t smem_u32(const void* p) {
    uint32_t a;
    asm("{ .reg .u64 t; cvta.to.shared.u64 t, %1; cvt.u32.u64 %0, t; }"
        : "=r"(a) : "l"(p));
    return a;
}
// packed f16x2 tanh (sm_75+, base target)
__device__ __forceinline__ __half2 tanh_h2(__half2 x) {
    __half2 y;
    asm("tanh.approx.f16x2 %0, %1;"
        : "=r"(*(uint32_t*)&y) : "r"(*(const uint32_t*)&x));
    return y;
}
// pack two f32 -> f16x2 {lo, hi}
__device__ __forceinline__ uint32_t f16x2(float hi, float lo) {
    uint32_t r;
    asm("cvt.rn.f16x2.f32 %0, %1, %2;" : "=r"(r) : "f"(hi), "f"(lo));
    return r;
}
__device__ __forceinline__ void ldmatrix_x4(uint32_t& r0, uint32_t& r1,
                                            uint32_t& r2, uint32_t& r3,
                                            uint32_t addr) {
    asm volatile("ldmatrix.sync.aligned.m8n8.x4.shared.b16 {%0,%1,%2,%3}, [%4];"
                 : "=r"(r0), "=r"(r1), "=r"(r2), "=r"(r3) : "r"(addr));
}
__device__ __forceinline__ void ldmatrix_x2(uint32_t& r0, uint32_t& r1,
                                            uint32_t addr) {
    asm volatile("ldmatrix.sync.aligned.m8n8.x2.shared.b16 {%0,%1}, [%2];"
                 : "=r"(r0), "=r"(r1) : "r"(addr));
}
__device__ __forceinline__ void mma16816(float* d, uint32_t a0, uint32_t a1,
                                         uint32_t a2, uint32_t a3,
                                         uint32_t b0, uint32_t b1) {
    asm volatile(
        "mma.sync.aligned.m16n8k16.row.col.f32.f16.f16.f32 "
        "{%0,%1,%2,%3}, {%4,%5,%6,%7}, {%8,%9}, {%0,%1,%2,%3};"
        : "+f"(d[0]), "+f"(d[1]), "+f"(d[2]), "+f"(d[3])
        : "r"(a0), "r"(a1), "r"(a2), "r"(a3), "r"(b0), "r"(b1));
}
__device__ __forceinline__ void mma16808(float* d, uint32_t a0, uint32_t a1,
                                         uint32_t b0) {
    asm volatile(
        "mma.sync.aligned.m16n8k8.row.col.f32.f16.f16.f32 "
        "{%0,%1,%2,%3}, {%4,%5}, {%6}, {%0,%1,%2,%3};"
        : "+f"(d[0]), "+f"(d[1]), "+f"(d[2]), "+f"(d[3])
        : "r"(a0), "r"(a1), "r"(b0));
}
__device__ __forceinline__ uint32_t sw128(uint32_t off) {
    return off ^ ((off >> 3) & 0x70);
}

// ---------------------------------------------------------------------------
// Problem constants
// ---------------------------------------------------------------------------
#define B_    4
#define T_    32
#define H_    64
#define W_    64
#define COUT_ 64
#define HW_   4096

// K layout: pair p = j = ci*9+kh*3+kw (0..26), halves = kd {t-1, t}.
// Pair 27: A = {1.0, 0}, B = {bias, 0}. MMA covers pairs 0..23 (3 x k16) + 24..27 (k8).
// B row n: tile8=n>>3, jj=n&7 -> cout c=(tile8>>1)*4+(jj>>1), gate=(tile8&1)*2+(jj&1)
// Warp split: mg = wid>>3 (64 px), nq8 = wid&7 (32 n-rows). B frags live in regs.

// SMEM layout (bytes)
#define SM_B_OFF    0                    // B fp16 [256 n][128 B]        = 32768
#define SM_A0_OFF   32768                // A fp16 buffer 0              = 16384
#define SM_A1_OFF   49152                // A fp16 buffer 1              = 16384
#define SM_HALO_OFF 65536                // halo 3 planes x 544 f32      = 6528
#define SM_TOTAL    72064
#define HPLANE      544

#define CT_ 512

__global__ void __launch_bounds__(CT_, 1)
fused_mma_kernel(const float* __restrict__ X,
                 const float* __restrict__ Wc, const float* __restrict__ bconv,
                 const float* __restrict__ Wci, const float* __restrict__ Wcf,
                 const float* __restrict__ Wco, float* __restrict__ out) {
    extern __shared__ __align__(1024) char sm[];
    const uint32_t smb = smem_u32(sm);
    float* hsm = (float*)(sm + SM_HALO_OFF);    // [plane = t mod 3][idx]

    const int tid  = threadIdx.x;
    const int wid  = tid >> 5;
    const int lane = tid & 31;
    const int mg   = wid >> 3;                  // M-half: 64 px
    const int nq8  = wid & 7;                   // N-eighth: 32 gate rows
    const int tile = blockIdx.x;
    const int b    = blockIdx.y;
    const int trow = (tile >> 3) * 16;
    const int tcol = (tile & 7) * 8;

    const float* Xb = X + (size_t)b * 3 * T_ * HW_;

    // ---- prologue: B weights + bias (fp16, SW128), A const cols in BOTH bufs ----
    for (int i = tid; i < 256 * 32; i += CT_) {
        int n = i >> 5;
        int p = i & 31;
        int tile8 = n >> 3;
        int jj    = n & 7;
        int c     = (tile8 >> 1) * 4 + (jj >> 1);
        int gate  = (tile8 & 1) * 2 + (jj & 1);
        int o     = gate * 64 + c;
        float v0 = 0.f, v1 = 0.f;
        if (p < 27) {
            int ci  = p / 9;
            int khw = p - ci * 9;
            v0 = Wc[o * 54 + ci * 18 + khw];
            v1 = Wc[o * 54 + ci * 18 + 9 + khw];
        } else if (p == 27) {
            v0 = bconv[o];
        }
        *(uint32_t*)(sm + SM_B_OFF + sw128((uint32_t)(n * 128 + p * 4))) = f16x2(v1, v0);
    }
    for (int i = tid; i < 128 * 5; i += CT_) {
        int px = i / 5;
        int p  = 27 + (i - px * 5);
        uint32_t v = (p == 27) ? f16x2(0.f, 1.f) : 0u;
        uint32_t arel = sw128((uint32_t)(px * 128 + p * 4));
        *(uint32_t*)(sm + SM_A0_OFF + arel) = v;
        *(uint32_t*)(sm + SM_A1_OFF + arel) = v;
    }

    // ---- halo prefetch descriptors (t-invariant) ----
    int h0idx, h0goff; bool h0ok;
    {
        int i  = tid;                   // 0..511 < 540
        int ci = i / 180;
        int rem = i - ci * 180;
        int rr = rem / 10;
        int cc = rem - rr * 10;
        int hh = trow - 1 + rr;
        int ww = tcol - 1 + cc;
        h0ok   = (hh >= 0 && hh < H_ && ww >= 0 && ww < W_);
        h0idx  = i;
        h0goff = ci * (T_ * HW_) + hh * W_ + ww;
    }
    int h1idx = 0, h1goff = 0; bool h1ok = false;
    if (tid < 28) {
        int i  = tid + 512;
        int ci = i / 180;
        int rem = i - ci * 180;
        int rr = rem / 10;
        int cc = rem - rr * 10;
        int hh = trow - 1 + rr;
        int ww = tcol - 1 + cc;
        h1ok   = (hh >= 0 && hh < H_ && ww >= 0 && ww < W_);
        h1idx  = i;
        h1goff = ci * (T_ * HW_) + hh * W_ + ww;
    }
    // planes: 0 <- x(0), 1 <- x(1), 2 <- 0 (x(-1); (-1) mod 3 == 2)
    hsm[h0idx]              = h0ok ? Xb[h0goff] : 0.f;
    hsm[HPLANE + h0idx]     = h0ok ? Xb[h0goff + HW_] : 0.f;
    hsm[2 * HPLANE + h0idx] = 0.f;
    if (tid < 28) {
        hsm[h1idx]              = h1ok ? Xb[h1goff] : 0.f;
        hsm[HPLANE + h1idx]     = h1ok ? Xb[h1goff + HW_] : 0.f;
        hsm[2 * HPLANE + h1idx] = 0.f;
    }

    // ---- A-build descriptors packed: (swizzled A-rel offset << 10) | halo idx ----
    uint32_t adesc[7];
#pragma unroll
    for (int k = 0; k < 7; k++) {
        int i = tid + k * CT_;
        if (i < 128 * 27) {
            int px = i / 27;
            int p  = i - px * 27;
            int ci  = p / 9;
            int khw = p - ci * 9;
            int kh  = khw / 3;
            int kw  = khw - kh * 3;
            uint32_t asoff = (uint32_t)(ci * 180 + ((px >> 3) + kh) * 10 + ((px & 7) + kw));
            uint32_t arel  = sw128((uint32_t)(px * 128 + p * 4));
            adesc[k] = (arel << 10) | asoff;
        } else {
            adesc[k] = 0xFFFFFFFFu;
        }
    }

    // ---- peephole params -> fp16 registers, paired over rs (pixel rows) ----
    // pair mp = mt*2 + gg: couts c = (nq8*2+gg)*4 + q, rows trow+mg*8+mt*2+{0,1}
    const int q  = lane & 3;
    const int lr = lane >> 2;
    const int r8 = lane & 7;
    const int g  = lane >> 3;

    __half2 wci2h[8], wcf2h[8], wco2h[8];
#pragma unroll
    for (int mp = 0; mp < 8; mp++) {
        int mt = mp >> 1;
        int gg = mp & 1;
        int c   = (nq8 * 2 + gg) * 4 + q;
        int hw0m = (trow + mg * 8 + mt * 2) * 64 + tcol + lr;      // rs = 0
        int hw1m = hw0m + 64;                                      // rs = 1
        wci2h[mp] = __floats2half2_rn(Wci[c * HW_ + hw0m], Wci[c * HW_ + hw1m]);
        wcf2h[mp] = __floats2half2_rn(Wcf[c * HW_ + hw0m], Wcf[c * HW_ + hw1m]);
        wco2h[mp] = __floats2half2_rn(Wco[c * HW_ + hw0m], Wco[c * HW_ + hw1m]);
    }
    __syncthreads();    // halo planes + B smem staged

    // ---- preload B fragments to registers (t-invariant!) ----
    const uint32_t cL  = (uint32_t)r8 << 4;
    const uint32_t dkA = (uint32_t)(g >> 1) * 16;
    const uint32_t dkB = (uint32_t)(g & 1) * 16;
    uint32_t Bf[24];    // [gg][kc][4]
    uint32_t Bt[4];     // [gg][2]
#pragma unroll
    for (int gg = 0; gg < 2; gg++) {
        uint32_t bb = smb + SM_B_OFF
                    + (uint32_t)(nq8 * 32 + gg * 16 + r8 + 8 * (g >> 1)) * 128;
#pragma unroll
        for (int kc = 0; kc < 3; kc++)
            ldmatrix_x4(Bf[gg*12+kc*4], Bf[gg*12+kc*4+1],
                        Bf[gg*12+kc*4+2], Bf[gg*12+kc*4+3],
                        bb + ((((uint32_t)kc * 32) + dkB) ^ cL));
        uint32_t bt = smb + SM_B_OFF
                    + (uint32_t)(nq8 * 32 + gg * 16 + (lane & 15)) * 128 + (96u ^ cL);
        ldmatrix_x2(Bt[gg*2], Bt[gg*2+1], bt);
    }

    // ---- prologue A-build(0) into buf 0: v0 = x(-1) (plane 2), v1 = x(0) ----
#pragma unroll
    for (int k = 0; k < 7; k++) {
        uint32_t d = adesc[k];
        if (d != 0xFFFFFFFFu) {
            uint32_t off = d & 1023;
            float v0 = hsm[2 * HPLANE + off];
            float v1 = hsm[off];
            *(uint32_t*)(sm + SM_A0_OFF + (d >> 10)) = f16x2(v1, v0);
        }
    }

    // ---- A ldmatrix lane-constant offsets (buf-relative) ----
    const uint32_t aRow4   = (uint32_t)(mg * 64 + r8 + 8 * (g & 1)) * 128;
    const uint32_t tailRow = (uint32_t)(mg * 64 + (lane & 15)) * 128 + (96u ^ cL);

    // ---- output base ----
    float* outb = out + ((size_t)(b * COUT_ + nq8 * 8 + q)) * (T_ * HW_)
                + (trow + mg * 8) * 64 + tcol + lr;
    const size_t ggstride = (size_t)4 * (T_ * HW_);   // cout += 4 per gg

    float C[16];
#pragma unroll
    for (int m = 0; m < 16; m++) C[m] = 0.f;

    float pf0 = 0.f, pf1 = 0.f;
    const __half2 h05 = __float2half2_rn(0.5f);

    for (int t = 0; t < T_; t++) {
        __syncthreads();   // A(t) built; halo plane (t+1)%3 stored; prior reads done

        const int pl0 = t % 3;              // x(t)
        const int pl1 = (t + 1) % 3;        // x(t+1)
        const int pl2 = (t + 2) % 3;        // store target for prefetch

        // ---- prefetch halo plane t+2 (LDG; stored at end of iter) ----
        if (t + 2 < T_) {
            const int toff = (t + 2) * HW_;
            pf0 = h0ok ? Xb[h0goff + toff] : 0.f;
            if (tid < 28) pf1 = h1ok ? Xb[h1goff + toff] : 0.f;
        }

        // ---- A-build(t+1) into buf[(t+1)&1] — overlaps MMA below ----
        if (t + 1 < T_) {
            char* ab = sm + SM_A0_OFF + (size_t)((t + 1) & 1) * 16384;
            const float* hb0 = hsm + pl0 * HPLANE;
            const float* hb1 = hsm + pl1 * HPLANE;
#pragma unroll
            for (int k = 0; k < 7; k++) {
                uint32_t d = adesc[k];
                if (d != 0xFFFFFFFFu) {
                    uint32_t off = d & 1023;
                    float v0 = hb0[off];    // x(t)   (kd=0 for step t+1)
                    float v1 = hb1[off];    // x(t+1) (kd=1)
                    *(uint32_t*)(ab + (d >> 10)) = f16x2(v1, v0);
                }
            }
        }

        // ---- per M16-tile: stream A, MMA vs reg-resident B, recurrence ----
        const uint32_t abuf = smb + (uint32_t)SM_A0_OFF + (uint32_t)(t & 1) * 16384;
        const size_t tof = (size_t)t * HW_;

#pragma unroll
        for (int mt = 0; mt < 4; mt++) {
            float acc[16];
#pragma unroll
            for (int m = 0; m < 16; m++) acc[m] = 0.f;

            const uint32_t aT = abuf + aRow4 + (uint32_t)mt * 2048;
#pragma unroll
            for (int kc = 0; kc < 3; kc++) {
                uint32_t a0, a1, a2, a3;
                ldmatrix_x4(a0, a1, a2, a3, aT + ((((uint32_t)kc * 32) + dkA) ^ cL));
                mma16816(acc,      a0, a1, a2, a3, Bf[kc*4],      Bf[kc*4+1]);
                mma16816(acc + 4,  a0, a1, a2, a3, Bf[kc*4+2],    Bf[kc*4+3]);
                mma16816(acc + 8,  a0, a1, a2, a3, Bf[12+kc*4],   Bf[12+kc*4+1]);
                mma16816(acc + 12, a0, a1, a2, a3, Bf[12+kc*4+2], Bf[12+kc*4+3]);
            }
            {   // k8 tail: pairs 24..27 (incl. bias)
                uint32_t at0, at1;
                ldmatrix_x2(at0, at1, abuf + tailRow + (uint32_t)mt * 2048);
                mma16808(acc,      at0, at1, Bt[0]);
                mma16808(acc + 4,  at0, at1, Bt[1]);
                mma16808(acc + 8,  at0, at1, Bt[2]);
                mma16808(acc + 12, at0, at1, Bt[3]);
            }

            // recurrence: 2 cout-groups x paired pixel rows (f16x2 activations)
            float* opt = outb + tof + (size_t)(mt * 2) * 64;
#pragma unroll
            for (int gg = 0; gg < 2; gg++) {
                const float* A = acc + gg * 8;   // [i0 f0 i1 f1 | g0 o0 g1 o1]
                const int mp = mt * 2 + gg;
                const int m0 = mt * 4 + gg * 2;

                __half2 Cp2 = __floats2half2_rn(C[m0], C[m0 + 1]);
                __half2 iv2 = __floats2half2_rn(A[0], A[2]);
                __half2 fv2 = __floats2half2_rn(A[1], A[3]);
                __half2 gv2 = __floats2half2_rn(A[4], A[6]);
                __half2 ov2 = __floats2half2_rn(A[5], A[7]);

                __half2 thi = tanh_h2(__hmul2(__hfma2(wci2h[mp], Cp2, iv2), h05));
                __half2 thf = tanh_h2(__hmul2(__hfma2(wcf2h[mp], Cp2, fv2), h05));
                __half2 tg  = tanh_h2(gv2);

                float2 igf = __half22float2(__hfma2(thi, h05, h05));
                float2 fgf = __half22float2(__hfma2(thf, h05, h05));
                float2 tgf = __half22float2(tg);

                float Cn0 = fgf.x * C[m0]     + igf.x * tgf.x;
                float Cn1 = fgf.y * C[m0 + 1] + igf.y * tgf.y;

                __half2 Cn2  = __floats2half2_rn(Cn0, Cn1);
                __half2 og2  = __hfma2(tanh_h2(__hmul2(__hfma2(wco2h[mp], Cn2, ov2), h05)),
                                       h05, h05);
                float2 Hf = __half22float2(__hmul2(og2, tanh_h2(Cn2)));

                opt[gg * ggstride]      = Hf.x;   // rs = 0
                opt[gg * ggstride + 64] = Hf.y;   // rs = 1
                C[m0]     = Cn0;
                C[m0 + 1] = Cn1;
            }
        }

        // ---- store prefetched halo(t+2) into plane pl2 (retired plane) ----
        if (t + 2 < T_) {
            hsm[pl2 * HPLANE + h0idx] = pf0;
            if (tid < 28) hsm[pl2 * HPLANE + h1idx] = pf1;
        }
    }
}

// ---------------------------------------------------------------------------
// kernel_launch
// ---------------------------------------------------------------------------
extern "C" void kernel_launch(void* const* d_in, const int* in_sizes, int n_in,
                              void* d_out, int out_size) {
    const float* X     = (const float*)d_in[0];
    const float* Wc    = (const float*)d_in[1];
    const float* bconv = (const float*)d_in[2];
    const float* Wci   = (const float*)d_in[3];
    const float* Wcf   = (const float*)d_in[4];
    const float* Wco   = (const float*)d_in[5];
    float* out = (float*)d_out;

    cudaFuncSetAttribute(fused_mma_kernel, cudaFuncAttributeMaxDynamicSharedMemorySize,
                         SM_TOTAL);

    dim3 grid(32, B_);   // 32 tiles x 4 batches = 128 CTAs (one wave)
    fused_mma_kernel<<<grid, CT_, SM_TOTAL>>>(X, Wc, bconv, Wci, Wcf, Wco, out);
}

// round 14
// speedup vs baseline: 1.0567x; 1.0567x over previous
#include <cuda_runtime.h>
#include <cuda_fp16.h>
#include <cstdint>
#include <cstddef>

// ---------------------------------------------------------------------------
// Portable PTX helpers (base sm_103 target: no 'a'-suffix instructions)
// ---------------------------------------------------------------------------
__device__ __forceinline__ uint32_t smem_u32(const void* p) {
    uint32_t a;
    asm("{ .reg .u64 t; cvta.to.shared.u64 t, %1; cvt.u32.u64 %0, t; }"
        : "=r"(a) : "l"(p));
    return a;
}
__device__ __forceinline__ float tanh_fast(float x) {
    float y;
    asm("tanh.approx.f32 %0, %1;" : "=f"(y) : "f"(x));
    return y;
}
__device__ __forceinline__ float sig_fast(float x) {
    return fmaf(0.5f, tanh_fast(0.5f * x), 0.5f);
}
// pack two f32 -> f16x2 {lo, hi}
__device__ __forceinline__ uint32_t f16x2(float hi, float lo) {
    uint32_t r;
    asm("cvt.rn.f16x2.f32 %0, %1, %2;" : "=r"(r) : "f"(hi), "f"(lo));
    return r;
}
__device__ __forceinline__ void ldmatrix_x4(uint32_t& r0, uint32_t& r1,
                                            uint32_t& r2, uint32_t& r3,
                                            uint32_t addr) {
    asm volatile("ldmatrix.sync.aligned.m8n8.x4.shared.b16 {%0,%1,%2,%3}, [%4];"
                 : "=r"(r0), "=r"(r1), "=r"(r2), "=r"(r3) : "r"(addr));
}
__device__ __forceinline__ void ldmatrix_x2(uint32_t& r0, uint32_t& r1,
                                            uint32_t addr) {
    asm volatile("ldmatrix.sync.aligned.m8n8.x2.shared.b16 {%0,%1}, [%2];"
                 : "=r"(r0), "=r"(r1) : "r"(addr));
}
__device__ __forceinline__ void mma16816(float* d, uint32_t a0, uint32_t a1,
                                         uint32_t a2, uint32_t a3,
                                         uint32_t b0, uint32_t b1) {
    asm volatile(
        "mma.sync.aligned.m16n8k16.row.col.f32.f16.f16.f32 "
        "{%0,%1,%2,%3}, {%4,%5,%6,%7}, {%8,%9}, {%0,%1,%2,%3};"
        : "+f"(d[0]), "+f"(d[1]), "+f"(d[2]), "+f"(d[3])
        : "r"(a0), "r"(a1), "r"(a2), "r"(a3), "r"(b0), "r"(b1));
}
__device__ __forceinline__ void mma16808(float* d, uint32_t a0, uint32_t a1,
                                         uint32_t b0) {
    asm volatile(
        "mma.sync.aligned.m16n8k8.row.col.f32.f16.f16.f32 "
        "{%0,%1,%2,%3}, {%4,%5}, {%6}, {%0,%1,%2,%3};"
        : "+f"(d[0]), "+f"(d[1]), "+f"(d[2]), "+f"(d[3])
        : "r"(a0), "r"(a1), "r"(b0));
}
__device__ __forceinline__ uint32_t sw128(uint32_t off) {
    return off ^ ((off >> 3) & 0x70);
}

// ---------------------------------------------------------------------------
// Problem constants
// ---------------------------------------------------------------------------
#define B_    4
#define T_    32
#define H_    64
#define W_    64
#define COUT_ 64
#define HW_   4096

// K layout: pair p = j = ci*9+kh*3+kw (0..26), halves = kd {t-1, t}.
// Pair 27: A = {1.0, 0}, B = {bias, 0}. MMA covers pairs 0..23 (3 x k16) + 24..27 (k8).
// B row n: tile8=n>>3, jj=n&7 -> cout c=(tile8>>1)*4+(jj>>1), gate=(tile8&1)*2+(jj&1)
// Warp split: mg = wid>>3 (64 px), nq8 = wid&7 (32 n-rows). B frags live in regs.
// Phase stagger: even wid processes mt 0->3, odd wid 3->0 (overlaps tensor & MUFU).

// SMEM layout (bytes)
#define SM_B_OFF    0                    // B fp16 [256 n][128 B]        = 32768
#define SM_A0_OFF   32768                // A fp16 buffer 0              = 16384
#define SM_A1_OFF   49152                // A fp16 buffer 1              = 16384
#define SM_HALO_OFF 65536                // halo 3 planes x 544 f32      = 6528
#define SM_TOTAL    72064
#define HPLANE      544

#define CT_ 512

__global__ void __launch_bounds__(CT_, 1)
fused_mma_kernel(const float* __restrict__ X,
                 const float* __restrict__ Wc, const float* __restrict__ bconv,
                 const float* __restrict__ Wci, const float* __restrict__ Wcf,
                 const float* __restrict__ Wco, float* __restrict__ out) {
    extern __shared__ __align__(1024) char sm[];
    const uint32_t smb = smem_u32(sm);
    float* hsm = (float*)(sm + SM_HALO_OFF);    // [plane = t mod 3][idx]

    const int tid  = threadIdx.x;
    const int wid  = tid >> 5;
    const int lane = tid & 31;
    const int mg   = wid >> 3;                  // M-half: 64 px
    const int nq8  = wid & 7;                   // N-eighth: 32 gate rows
    const int tile = blockIdx.x;
    const int b    = blockIdx.y;
    const int trow = (tile >> 3) * 16;
    const int tcol = (tile & 7) * 8;

    const float* Xb = X + (size_t)b * 3 * T_ * HW_;

    // ---- prologue: B weights + bias (fp16, SW128), A const cols in BOTH bufs ----
    for (int i = tid; i < 256 * 32; i += CT_) {
        int n = i >> 5;
        int p = i & 31;
        int tile8 = n >> 3;
        int jj    = n & 7;
        int c     = (tile8 >> 1) * 4 + (jj >> 1);
        int gate  = (tile8 & 1) * 2 + (jj & 1);
        int o     = gate * 64 + c;
        float v0 = 0.f, v1 = 0.f;
        if (p < 27) {
            int ci  = p / 9;
            int khw = p - ci * 9;
            v0 = Wc[o * 54 + ci * 18 + khw];
            v1 = Wc[o * 54 + ci * 18 + 9 + khw];
        } else if (p == 27) {
            v0 = bconv[o];
        }
        *(uint32_t*)(sm + SM_B_OFF + sw128((uint32_t)(n * 128 + p * 4))) = f16x2(v1, v0);
    }
    for (int i = tid; i < 128 * 5; i += CT_) {
        int px = i / 5;
        int p  = 27 + (i - px * 5);
        uint32_t v = (p == 27) ? f16x2(0.f, 1.f) : 0u;
        uint32_t arel = sw128((uint32_t)(px * 128 + p * 4));
        *(uint32_t*)(sm + SM_A0_OFF + arel) = v;
        *(uint32_t*)(sm + SM_A1_OFF + arel) = v;
    }

    // ---- halo prefetch descriptors (t-invariant) ----
    int h0idx, h0goff; bool h0ok;
    {
        int i  = tid;                   // 0..511 < 540
        int ci = i / 180;
        int rem = i - ci * 180;
        int rr = rem / 10;
        int cc = rem - rr * 10;
        int hh = trow - 1 + rr;
        int ww = tcol - 1 + cc;
        h0ok   = (hh >= 0 && hh < H_ && ww >= 0 && ww < W_);
        h0idx  = i;
        h0goff = ci * (T_ * HW_) + hh * W_ + ww;
    }
    int h1idx = 0, h1goff = 0; bool h1ok = false;
    if (tid < 28) {
        int i  = tid + 512;
        int ci = i / 180;
        int rem = i - ci * 180;
        int rr = rem / 10;
        int cc = rem - rr * 10;
        int hh = trow - 1 + rr;
        int ww = tcol - 1 + cc;
        h1ok   = (hh >= 0 && hh < H_ && ww >= 0 && ww < W_);
        h1idx  = i;
        h1goff = ci * (T_ * HW_) + hh * W_ + ww;
    }
    // planes: 0 <- x(0), 1 <- x(1), 2 <- 0 (x(-1); (-1) mod 3 == 2)
    hsm[h0idx]              = h0ok ? Xb[h0goff] : 0.f;
    hsm[HPLANE + h0idx]     = h0ok ? Xb[h0goff + HW_] : 0.f;
    hsm[2 * HPLANE + h0idx] = 0.f;
    if (tid < 28) {
        hsm[h1idx]              = h1ok ? Xb[h1goff] : 0.f;
        hsm[HPLANE + h1idx]     = h1ok ? Xb[h1goff + HW_] : 0.f;
        hsm[2 * HPLANE + h1idx] = 0.f;
    }

    // ---- A-build descriptors packed: (swizzled A-rel offset << 10) | halo idx ----
    uint32_t adesc[7];
#pragma unroll
    for (int k = 0; k < 7; k++) {
        int i = tid + k * CT_;
        if (i < 128 * 27) {
            int px = i / 27;
            int p  = i - px * 27;
            int ci  = p / 9;
            int khw = p - ci * 9;
            int kh  = khw / 3;
            int kw  = khw - kh * 3;
            uint32_t asoff = (uint32_t)(ci * 180 + ((px >> 3) + kh) * 10 + ((px & 7) + kw));
            uint32_t arel  = sw128((uint32_t)(px * 128 + p * 4));
            adesc[k] = (arel << 10) | asoff;
        } else {
            adesc[k] = 0xFFFFFFFFu;
        }
    }

    // ---- peephole params -> fp16 registers ----
    // cell m = mt*4 + gg*2 + rs: cout c = (nq8*2+gg)*4 + q,
    //   pixel (h,w) = (trow + mg*8 + mt*2 + rs, tcol + lr)
    const int q  = lane & 3;
    const int lr = lane >> 2;
    const int r8 = lane & 7;
    const int g  = lane >> 3;

    __half2 wifh[16];
    __half2 wcoh[8];
    {
        float wcot[16];
#pragma unroll
        for (int m = 0; m < 16; m++) {
            int mt = m >> 2;
            int gg = (m >> 1) & 1;
            int rs = m & 1;
            int c   = (nq8 * 2 + gg) * 4 + q;
            int hwm = (trow + mg * 8 + mt * 2 + rs) * 64 + tcol + lr;
            wifh[m] = __floats2half2_rn(Wci[c * HW_ + hwm], Wcf[c * HW_ + hwm]);
            wcot[m] = Wco[c * HW_ + hwm];
        }
#pragma unroll
        for (int j = 0; j < 8; j++)
            wcoh[j] = __floats2half2_rn(wcot[2 * j], wcot[2 * j + 1]);
    }
    __syncthreads();    // halo planes + B smem staged

    // ---- preload B fragments to registers (t-invariant!) ----
    const uint32_t cL  = (uint32_t)r8 << 4;
    const uint32_t dkA = (uint32_t)(g >> 1) * 16;
    const uint32_t dkB = (uint32_t)(g & 1) * 16;
    uint32_t Bf[24];    // [gg][kc][4]
    uint32_t Bt[4];     // [gg][2]
#pragma unroll
    for (int gg = 0; gg < 2; gg++) {
        uint32_t bb = smb + SM_B_OFF
                    + (uint32_t)(nq8 * 32 + gg * 16 + r8 + 8 * (g >> 1)) * 128;
#pragma unroll
        for (int kc = 0; kc < 3; kc++)
            ldmatrix_x4(Bf[gg*12+kc*4], Bf[gg*12+kc*4+1],
                        Bf[gg*12+kc*4+2], Bf[gg*12+kc*4+3],
                        bb + ((((uint32_t)kc * 32) + dkB) ^ cL));
        uint32_t bt = smb + SM_B_OFF
                    + (uint32_t)(nq8 * 32 + gg * 16 + (lane & 15)) * 128 + (96u ^ cL);
        ldmatrix_x2(Bt[gg*2], Bt[gg*2+1], bt);
    }

    // ---- prologue A-build(0) into buf 0: v0 = x(-1) (plane 2), v1 = x(0) ----
#pragma unroll
    for (int k = 0; k < 7; k++) {
        uint32_t d = adesc[k];
        if (d != 0xFFFFFFFFu) {
            uint32_t off = d & 1023;
            float v0 = hsm[2 * HPLANE + off];
            float v1 = hsm[off];
            *(uint32_t*)(sm + SM_A0_OFF + (d >> 10)) = f16x2(v1, v0);
        }
    }

    // ---- A ldmatrix lane-constant offsets (buf-relative) ----
    const uint32_t aRow4   = (uint32_t)(mg * 64 + r8 + 8 * (g & 1)) * 128;
    const uint32_t tailRow = (uint32_t)(mg * 64 + (lane & 15)) * 128 + (96u ^ cL);

    // ---- output base ----
    float* outb = out + ((size_t)(b * COUT_ + nq8 * 8 + q)) * (T_ * HW_)
                + (trow + mg * 8) * 64 + tcol + lr;
    const size_t ggstride = (size_t)4 * (T_ * HW_);   // cout += 4 per gg

    float C[16];
#pragma unroll
    for (int m = 0; m < 16; m++) C[m] = 0.f;

    float pf0 = 0.f, pf1 = 0.f;
    const bool rev = (wid & 1);

    for (int t = 0; t < T_; t++) {
        __syncthreads();   // A(t) built; halo plane (t+1)%3 stored; prior reads done

        const int pl0 = t % 3;              // x(t)
        const int pl1 = (t + 1) % 3;        // x(t+1)
        const int pl2 = (t + 2) % 3;        // store target for prefetch

        // ---- prefetch halo plane t+2 (LDG; stored at end of iter) ----
        if (t + 2 < T_) {
            const int toff = (t + 2) * HW_;
            pf0 = h0ok ? Xb[h0goff + toff] : 0.f;
            if (tid < 28) pf1 = h1ok ? Xb[h1goff + toff] : 0.f;
        }

        // ---- A-build(t+1) into buf[(t+1)&1] — overlaps MMA below ----
        if (t + 1 < T_) {
            char* ab = sm + SM_A0_OFF + (size_t)((t + 1) & 1) * 16384;
            const float* hb0 = hsm + pl0 * HPLANE;
            const float* hb1 = hsm + pl1 * HPLANE;
#pragma unroll
            for (int k = 0; k < 7; k++) {
                uint32_t d = adesc[k];
                if (d != 0xFFFFFFFFu) {
                    uint32_t off = d & 1023;
                    float v0 = hb0[off];    // x(t)   (kd=0 for step t+1)
                    float v1 = hb1[off];    // x(t+1) (kd=1)
                    *(uint32_t*)(ab + (d >> 10)) = f16x2(v1, v0);
                }
            }
        }

        // ---- per M16-tile: stream A, MMA vs reg-resident B, recurrence ----
        const uint32_t abuf = smb + (uint32_t)SM_A0_OFF + (uint32_t)(t & 1) * 16384;
        const size_t tof = (size_t)t * HW_;

        auto mt_step = [&](const int mt) {
            float acc[16];
#pragma unroll
            for (int m = 0; m < 16; m++) acc[m] = 0.f;

            const uint32_t aT = abuf + aRow4 + (uint32_t)mt * 2048;
#pragma unroll
            for (int kc = 0; kc < 3; kc++) {
                uint32_t a0, a1, a2, a3;
                ldmatrix_x4(a0, a1, a2, a3, aT + ((((uint32_t)kc * 32) + dkA) ^ cL));
                mma16816(acc,      a0, a1, a2, a3, Bf[kc*4],      Bf[kc*4+1]);
                mma16816(acc + 4,  a0, a1, a2, a3, Bf[kc*4+2],    Bf[kc*4+3]);
                mma16816(acc + 8,  a0, a1, a2, a3, Bf[12+kc*4],   Bf[12+kc*4+1]);
                mma16816(acc + 12, a0, a1, a2, a3, Bf[12+kc*4+2], Bf[12+kc*4+3]);
            }
            {   // k8 tail: pairs 24..27 (incl. bias)
                uint32_t at0, at1;
                ldmatrix_x2(at0, at1, abuf + tailRow + (uint32_t)mt * 2048);
                mma16808(acc,      at0, at1, Bt[0]);
                mma16808(acc + 4,  at0, at1, Bt[1]);
                mma16808(acc + 8,  at0, at1, Bt[2]);
                mma16808(acc + 12, at0, at1, Bt[3]);
            }

            // recurrence: 4 cells = 2 cout-groups x 2 pixel rows
            float* opt = outb + tof + (size_t)(mt * 2) * 64;
#pragma unroll
            for (int gg = 0; gg < 2; gg++) {
                const float* A = acc + gg * 8;   // [i0 f0 i1 f1 | g0 o0 g1 o1]
#pragma unroll
                for (int rs = 0; rs < 2; rs++) {
                    const int m = mt * 4 + gg * 2 + rs;
                    float iv = A[rs * 2];
                    float fv = A[rs * 2 + 1];
                    float gv = A[4 + rs * 2];
                    float ov = A[5 + rs * 2];
                    float2 wif = __half22float2(wifh[m]);
                    float wco  = rs ? __high2float(wcoh[m >> 1])
                                    : __low2float(wcoh[m >> 1]);
                    float Cp = C[m];
                    float ig = sig_fast(iv + wif.x * Cp);
                    float fg = sig_fast(fv + wif.y * Cp);
                    float Cn = fg * Cp + ig * tanh_fast(gv);
                    float og = sig_fast(ov + wco * Cn);
                    opt[gg * ggstride + (size_t)rs * 64] = og * tanh_fast(Cn);
                    C[m] = Cn;
                }
            }
        };

        // stagger phases across warps: odd warps run mt in reverse order so
        // their tensor/ldmatrix phase overlaps even warps' MUFU phase
        if (rev) { mt_step(3); mt_step(2); mt_step(1); mt_step(0); }
        else     { mt_step(0); mt_step(1); mt_step(2); mt_step(3); }

        // ---- store prefetched halo(t+2) into plane pl2 (retired plane) ----
        if (t + 2 < T_) {
            hsm[pl2 * HPLANE + h0idx] = pf0;
            if (tid < 28) hsm[pl2 * HPLANE + h1idx] = pf1;
        }
    }
}

// ---------------------------------------------------------------------------
// kernel_launch
// ---------------------------------------------------------------------------
extern "C" void kernel_launch(void* const* d_in, const int* in_sizes, int n_in,
                              void* d_out, int out_size) {
    const float* X     = (const float*)d_in[0];
    const float* Wc    = (const float*)d_in[1];
    const float* bconv = (const float*)d_in[2];
    const float* Wci   = (const float*)d_in[3];
    const float* Wcf   = (const float*)d_in[4];
    const float* Wco   = (const float*)d_in[5];
    float* out = (float*)d_out;

    cudaFuncSetAttribute(fused_mma_kernel, cudaFuncAttributeMaxDynamicSharedMemorySize,
                         SM_TOTAL);

    dim3 grid(32, B_);   // 32 tiles x 4 batches = 128 CTAs (one wave)
    fused_mma_kernel<<<grid, CT_, SM_TOTAL>>>(X, Wc, bconv, Wci, Wcf, Wco, out);
}

// round 15
// speedup vs baseline: 1.0632x; 1.0062x over previous
#include <cuda_runtime.h>
#include <cuda_fp16.h>
#include <cstdint>
#include <cstddef>

// ---------------------------------------------------------------------------
// Portable PTX helpers (base sm_103 target: no 'a'-suffix instructions)
// ---------------------------------------------------------------------------
__device__ __forceinline__ uint32_t smem_u32(const void* p) {
    uint32_t a;
    asm("{ .reg .u64 t; cvta.to.shared.u64 t, %1; cvt.u32.u64 %0, t; }"
        : "=r"(a) : "l"(p));
    return a;
}
__device__ __forceinline__ float tanh_fast(float x) {
    float y;
    asm("tanh.approx.f32 %0, %1;" : "=f"(y) : "f"(x));
    return y;
}
__device__ __forceinline__ float sig_fast(float x) {
    return fmaf(0.5f, tanh_fast(0.5f * x), 0.5f);
}
// pack two f32 -> f16x2 {lo, hi}
__device__ __forceinline__ uint32_t f16x2(float hi, float lo) {
    uint32_t r;
    asm("cvt.rn.f16x2.f32 %0, %1, %2;" : "=r"(r) : "f"(hi), "f"(lo));
    return r;
}
__device__ __forceinline__ void ldmatrix_x4(uint32_t& r0, uint32_t& r1,
                                            uint32_t& r2, uint32_t& r3,
                                            uint32_t addr) {
    asm volatile("ldmatrix.sync.aligned.m8n8.x4.shared.b16 {%0,%1,%2,%3}, [%4];"
                 : "=r"(r0), "=r"(r1), "=r"(r2), "=r"(r3) : "r"(addr));
}
__device__ __forceinline__ void ldmatrix_x2(uint32_t& r0, uint32_t& r1,
                                            uint32_t addr) {
    asm volatile("ldmatrix.sync.aligned.m8n8.x2.shared.b16 {%0,%1}, [%2];"
                 : "=r"(r0), "=r"(r1) : "r"(addr));
}
__device__ __forceinline__ void mma16816(float* d, uint32_t a0, uint32_t a1,
                                         uint32_t a2, uint32_t a3,
                                         uint32_t b0, uint32_t b1) {
    asm volatile(
        "mma.sync.aligned.m16n8k16.row.col.f32.f16.f16.f32 "
        "{%0,%1,%2,%3}, {%4,%5,%6,%7}, {%8,%9}, {%0,%1,%2,%3};"
        : "+f"(d[0]), "+f"(d[1]), "+f"(d[2]), "+f"(d[3])
        : "r"(a0), "r"(a1), "r"(a2), "r"(a3), "r"(b0), "r"(b1));
}
__device__ __forceinline__ void mma16808(float* d, uint32_t a0, uint32_t a1,
                                         uint32_t b0) {
    asm volatile(
        "mma.sync.aligned.m16n8k8.row.col.f32.f16.f16.f32 "
        "{%0,%1,%2,%3}, {%4,%5}, {%6}, {%0,%1,%2,%3};"
        : "+f"(d[0]), "+f"(d[1]), "+f"(d[2]), "+f"(d[3])
        : "r"(a0), "r"(a1), "r"(b0));
}
__device__ __forceinline__ uint32_t sw128(uint32_t off) {
    return off ^ ((off >> 3) & 0x70);
}

// ---------------------------------------------------------------------------
// Problem constants
// ---------------------------------------------------------------------------
#define B_    4
#define T_    32
#define H_    64
#define W_    64
#define COUT_ 64
#define HW_   4096

// K layout: pair p = j = ci*9+kh*3+kw (0..26), halves = kd {t-1, t}.
// Pair 27: A = {1.0, 0}, B = {bias, 0}. MMA covers pairs 0..23 (3 x k16) + 24..27 (k8).
// B row n: tile8=n>>3, jj=n&7 -> cout c=(tile8>>1)*4+(jj>>1), gate=(tile8&1)*2+(jj&1)
// Warp split: mg = wid>>3 (64 px), nq8 = wid&7 (32 n-rows). B frags live in regs.
// Phase stagger: rev = (wid>>2)&1 — SMSP k holds wids {k,k+4,k+8,k+12}, so each
// SMSP gets 2 forward + 2 reverse warps: tensor phase of one pair overlaps the
// MUFU phase of the other.

// SMEM layout (bytes)
#define SM_B_OFF    0                    // B fp16 [256 n][128 B]        = 32768
#define SM_A0_OFF   32768                // A fp16 buffer 0              = 16384
#define SM_A1_OFF   49152                // A fp16 buffer 1              = 16384
#define SM_HALO_OFF 65536                // halo 3 planes x 544 f32      = 6528
#define SM_TOTAL    72064
#define HPLANE      544

#define CT_ 512

__global__ void __launch_bounds__(CT_, 1)
fused_mma_kernel(const float* __restrict__ X,
                 const float* __restrict__ Wc, const float* __restrict__ bconv,
                 const float* __restrict__ Wci, const float* __restrict__ Wcf,
                 const float* __restrict__ Wco, float* __restrict__ out) {
    extern __shared__ __align__(1024) char sm[];
    const uint32_t smb = smem_u32(sm);
    float* hsm = (float*)(sm + SM_HALO_OFF);    // [plane = t mod 3][idx]

    const int tid  = threadIdx.x;
    const int wid  = tid >> 5;
    const int lane = tid & 31;
    const int mg   = wid >> 3;                  // M-half: 64 px
    const int nq8  = wid & 7;                   // N-eighth: 32 gate rows
    const int tile = blockIdx.x;
    const int b    = blockIdx.y;
    const int trow = (tile >> 3) * 16;
    const int tcol = (tile & 7) * 8;

    const float* Xb = X + (size_t)b * 3 * T_ * HW_;

    // ---- prologue: B weights + bias (fp16, SW128), A const cols in BOTH bufs ----
    for (int i = tid; i < 256 * 32; i += CT_) {
        int n = i >> 5;
        int p = i & 31;
        int tile8 = n >> 3;
        int jj    = n & 7;
        int c     = (tile8 >> 1) * 4 + (jj >> 1);
        int gate  = (tile8 & 1) * 2 + (jj & 1);
        int o     = gate * 64 + c;
        float v0 = 0.f, v1 = 0.f;
        if (p < 27) {
            int ci  = p / 9;
            int khw = p - ci * 9;
            v0 = Wc[o * 54 + ci * 18 + khw];
            v1 = Wc[o * 54 + ci * 18 + 9 + khw];
        } else if (p == 27) {
            v0 = bconv[o];
        }
        *(uint32_t*)(sm + SM_B_OFF + sw128((uint32_t)(n * 128 + p * 4))) = f16x2(v1, v0);
    }
    for (int i = tid; i < 128 * 5; i += CT_) {
        int px = i / 5;
        int p  = 27 + (i - px * 5);
        uint32_t v = (p == 27) ? f16x2(0.f, 1.f) : 0u;
        uint32_t arel = sw128((uint32_t)(px * 128 + p * 4));
        *(uint32_t*)(sm + SM_A0_OFF + arel) = v;
        *(uint32_t*)(sm + SM_A1_OFF + arel) = v;
    }

    // ---- halo prefetch descriptors (t-invariant) ----
    int h0idx, h0goff; bool h0ok;
    {
        int i  = tid;                   // 0..511 < 540
        int ci = i / 180;
        int rem = i - ci * 180;
        int rr = rem / 10;
        int cc = rem - rr * 10;
        int hh = trow - 1 + rr;
        int ww = tcol - 1 + cc;
        h0ok   = (hh >= 0 && hh < H_ && ww >= 0 && ww < W_);
        h0idx  = i;
        h0goff = ci * (T_ * HW_) + hh * W_ + ww;
    }
    int h1idx = 0, h1goff = 0; bool h1ok = false;
    if (tid < 28) {
        int i  = tid + 512;
        int ci = i / 180;
        int rem = i - ci * 180;
        int rr = rem / 10;
        int cc = rem - rr * 10;
        int hh = trow - 1 + rr;
        int ww = tcol - 1 + cc;
        h1ok   = (hh >= 0 && hh < H_ && ww >= 0 && ww < W_);
        h1idx  = i;
        h1goff = ci * (T_ * HW_) + hh * W_ + ww;
    }
    // planes: 0 <- x(0), 1 <- x(1), 2 <- 0 (x(-1); (-1) mod 3 == 2)
    hsm[h0idx]              = h0ok ? Xb[h0goff] : 0.f;
    hsm[HPLANE + h0idx]     = h0ok ? Xb[h0goff + HW_] : 0.f;
    hsm[2 * HPLANE + h0idx] = 0.f;
    if (tid < 28) {
        hsm[h1idx]              = h1ok ? Xb[h1goff] : 0.f;
        hsm[HPLANE + h1idx]     = h1ok ? Xb[h1goff + HW_] : 0.f;
        hsm[2 * HPLANE + h1idx] = 0.f;
    }

    // ---- A-build descriptors packed: (swizzled A-rel offset << 10) | halo idx ----
    uint32_t adesc[7];
#pragma unroll
    for (int k = 0; k < 7; k++) {
        int i = tid + k * CT_;
        if (i < 128 * 27) {
            int px = i / 27;
            int p  = i - px * 27;
            int ci  = p / 9;
            int khw = p - ci * 9;
            int kh  = khw / 3;
            int kw  = khw - kh * 3;
            uint32_t asoff = (uint32_t)(ci * 180 + ((px >> 3) + kh) * 10 + ((px & 7) + kw));
            uint32_t arel  = sw128((uint32_t)(px * 128 + p * 4));
            adesc[k] = (arel << 10) | asoff;
        } else {
            adesc[k] = 0xFFFFFFFFu;
        }
    }

    // ---- peephole params -> fp16 registers ----
    // cell m = mt*4 + gg*2 + rs: cout c = (nq8*2+gg)*4 + q,
    //   pixel (h,w) = (trow + mg*8 + mt*2 + rs, tcol + lr)
    const int q  = lane & 3;
    const int lr = lane >> 2;
    const int r8 = lane & 7;
    const int g  = lane >> 3;

    __half2 wifh[16];
    __half2 wcoh[8];
    {
        float wcot[16];
#pragma unroll
        for (int m = 0; m < 16; m++) {
            int mt = m >> 2;
            int gg = (m >> 1) & 1;
            int rs = m & 1;
            int c   = (nq8 * 2 + gg) * 4 + q;
            int hwm = (trow + mg * 8 + mt * 2 + rs) * 64 + tcol + lr;
            wifh[m] = __floats2half2_rn(Wci[c * HW_ + hwm], Wcf[c * HW_ + hwm]);
            wcot[m] = Wco[c * HW_ + hwm];
        }
#pragma unroll
        for (int j = 0; j < 8; j++)
            wcoh[j] = __floats2half2_rn(wcot[2 * j], wcot[2 * j + 1]);
    }
    __syncthreads();    // halo planes + B smem staged

    // ---- preload B fragments to registers (t-invariant!) ----
    const uint32_t cL  = (uint32_t)r8 << 4;
    const uint32_t dkA = (uint32_t)(g >> 1) * 16;
    const uint32_t dkB = (uint32_t)(g & 1) * 16;
    uint32_t Bf[24];    // [gg][kc][4]
    uint32_t Bt[4];     // [gg][2]
#pragma unroll
    for (int gg = 0; gg < 2; gg++) {
        uint32_t bb = smb + SM_B_OFF
                    + (uint32_t)(nq8 * 32 + gg * 16 + r8 + 8 * (g >> 1)) * 128;
#pragma unroll
        for (int kc = 0; kc < 3; kc++)
            ldmatrix_x4(Bf[gg*12+kc*4], Bf[gg*12+kc*4+1],
                        Bf[gg*12+kc*4+2], Bf[gg*12+kc*4+3],
                        bb + ((((uint32_t)kc * 32) + dkB) ^ cL));
        uint32_t bt = smb + SM_B_OFF
                    + (uint32_t)(nq8 * 32 + gg * 16 + (lane & 15)) * 128 + (96u ^ cL);
        ldmatrix_x2(Bt[gg*2], Bt[gg*2+1], bt);
    }

    // ---- prologue A-build(0) into buf 0: v0 = x(-1) (plane 2), v1 = x(0) ----
#pragma unroll
    for (int k = 0; k < 7; k++) {
        uint32_t d = adesc[k];
        if (d != 0xFFFFFFFFu) {
            uint32_t off = d & 1023;
            float v0 = hsm[2 * HPLANE + off];
            float v1 = hsm[off];
            *(uint32_t*)(sm + SM_A0_OFF + (d >> 10)) = f16x2(v1, v0);
        }
    }

    // ---- A ldmatrix lane-constant offsets (buf-relative) ----
    const uint32_t aRow4   = (uint32_t)(mg * 64 + r8 + 8 * (g & 1)) * 128;
    const uint32_t tailRow = (uint32_t)(mg * 64 + (lane & 15)) * 128 + (96u ^ cL);

    // ---- output base ----
    float* outb = out + ((size_t)(b * COUT_ + nq8 * 8 + q)) * (T_ * HW_)
                + (trow + mg * 8) * 64 + tcol + lr;
    const size_t ggstride = (size_t)4 * (T_ * HW_);   // cout += 4 per gg

    float C[16];
#pragma unroll
    for (int m = 0; m < 16; m++) C[m] = 0.f;

    float pf0 = 0.f, pf1 = 0.f;
    // SMSP = wid%4 holds wids {smsp, smsp+4, smsp+8, smsp+12}; key the phase
    // reversal on (wid>>2)&1 so each SMSP gets 2 forward + 2 reverse warps.
    const bool rev = ((wid >> 2) & 1);

    for (int t = 0; t < T_; t++) {
        __syncthreads();   // A(t) built; halo plane (t+1)%3 stored; prior reads done

        const int pl0 = t % 3;              // x(t)
        const int pl1 = (t + 1) % 3;        // x(t+1)
        const int pl2 = (t + 2) % 3;        // store target for prefetch

        // ---- prefetch halo plane t+2 (LDG; stored at end of iter) ----
        if (t + 2 < T_) {
            const int toff = (t + 2) * HW_;
            pf0 = h0ok ? Xb[h0goff + toff] : 0.f;
            if (tid < 28) pf1 = h1ok ? Xb[h1goff + toff] : 0.f;
        }

        // ---- A-build(t+1) into buf[(t+1)&1] — overlaps MMA below ----
        if (t + 1 < T_) {
            char* ab = sm + SM_A0_OFF + (size_t)((t + 1) & 1) * 16384;
            const float* hb0 = hsm + pl0 * HPLANE;
            const float* hb1 = hsm + pl1 * HPLANE;
#pragma unroll
            for (int k = 0; k < 7; k++) {
                uint32_t d = adesc[k];
                if (d != 0xFFFFFFFFu) {
                    uint32_t off = d & 1023;
                    float v0 = hb0[off];    // x(t)   (kd=0 for step t+1)
                    float v1 = hb1[off];    // x(t+1) (kd=1)
                    *(uint32_t*)(ab + (d >> 10)) = f16x2(v1, v0);
                }
            }
        }

        // ---- per M16-tile: stream A, MMA vs reg-resident B, recurrence ----
        const uint32_t abuf = smb + (uint32_t)SM_A0_OFF + (uint32_t)(t & 1) * 16384;
        const size_t tof = (size_t)t * HW_;

        auto mt_step = [&](const int mt) {
            float acc[16];
#pragma unroll
            for (int m = 0; m < 16; m++) acc[m] = 0.f;

            const uint32_t aT = abuf + aRow4 + (uint32_t)mt * 2048;
#pragma unroll
            for (int kc = 0; kc < 3; kc++) {
                uint32_t a0, a1, a2, a3;
                ldmatrix_x4(a0, a1, a2, a3, aT + ((((uint32_t)kc * 32) + dkA) ^ cL));
                mma16816(acc,      a0, a1, a2, a3, Bf[kc*4],      Bf[kc*4+1]);
                mma16816(acc + 4,  a0, a1, a2, a3, Bf[kc*4+2],    Bf[kc*4+3]);
                mma16816(acc + 8,  a0, a1, a2, a3, Bf[12+kc*4],   Bf[12+kc*4+1]);
                mma16816(acc + 12, a0, a1, a2, a3, Bf[12+kc*4+2], Bf[12+kc*4+3]);
            }
            {   // k8 tail: pairs 24..27 (incl. bias)
                uint32_t at0, at1;
                ldmatrix_x2(at0, at1, abuf + tailRow + (uint32_t)mt * 2048);
                mma16808(acc,      at0, at1, Bt[0]);
                mma16808(acc + 4,  at0, at1, Bt[1]);
                mma16808(acc + 8,  at0, at1, Bt[2]);
                mma16808(acc + 12, at0, at1, Bt[3]);
            }

            // recurrence: 4 cells = 2 cout-groups x 2 pixel rows
            float* opt = outb + tof + (size_t)(mt * 2) * 64;
#pragma unroll
            for (int gg = 0; gg < 2; gg++) {
                const float* A = acc + gg * 8;   // [i0 f0 i1 f1 | g0 o0 g1 o1]
#pragma unroll
                for (int rs = 0; rs < 2; rs++) {
                    const int m = mt * 4 + gg * 2 + rs;
                    float iv = A[rs * 2];
                    float fv = A[rs * 2 + 1];
                    float gv = A[4 + rs * 2];
                    float ov = A[5 + rs * 2];
                    float2 wif = __half22float2(wifh[m]);
                    float wco  = rs ? __high2float(wcoh[m >> 1])
                                    : __low2float(wcoh[m >> 1]);
                    float Cp = C[m];
                    float ig = sig_fast(iv + wif.x * Cp);
                    float fg = sig_fast(fv + wif.y * Cp);
                    float Cn = fg * Cp + ig * tanh_fast(gv);
                    float og = sig_fast(ov + wco * Cn);
                    opt[gg * ggstride + (size_t)rs * 64] = og * tanh_fast(Cn);
                    C[m] = Cn;
                }
            }
        };

        // stagger phases WITHIN each SMSP: 2 of its 4 warps run mt in reverse,
        // overlapping their tensor/ldmatrix phase with the others' MUFU phase
        if (rev) { mt_step(3); mt_step(2); mt_step(1); mt_step(0); }
        else     { mt_step(0); mt_step(1); mt_step(2); mt_step(3); }

        // ---- store prefetched halo(t+2) into plane pl2 (retired plane) ----
        if (t + 2 < T_) {
            hsm[pl2 * HPLANE + h0idx] = pf0;
            if (tid < 28) hsm[pl2 * HPLANE + h1idx] = pf1;
        }
    }
}

// ---------------------------------------------------------------------------
// kernel_launch
// ---------------------------------------------------------------------------
extern "C" void kernel_launch(void* const* d_in, const int* in_sizes, int n_in,
                              void* d_out, int out_size) {
    const float* X     = (const float*)d_in[0];
    const float* Wc    = (const float*)d_in[1];
    const float* bconv = (const float*)d_in[2];
    const float* Wci   = (const float*)d_in[3];
    const float* Wcf   = (const float*)d_in[4];
    const float* Wco   = (const float*)d_in[5];
    float* out = (float*)d_out;

    cudaFuncSetAttribute(fused_mma_kernel, cudaFuncAttributeMaxDynamicSharedMemorySize,
                         SM_TOTAL);

    dim3 grid(32, B_);   // 32 tiles x 4 batches = 128 CTAs (one wave)
    fused_mma_kernel<<<grid, CT_, SM_TOTAL>>>(X, Wc, bconv, Wci, Wcf, Wco, out);
}

// round 16
// speedup vs baseline: 1.0687x; 1.0052x over previous
#include <cuda_runtime.h>
#include <cuda_fp16.h>
#include <cstdint>
#include <cstddef>

// ---------------------------------------------------------------------------
// Portable PTX helpers (base sm_103 target: no 'a'-suffix instructions)
// ---------------------------------------------------------------------------
__device__ __forceinline__ uint32_t smem_u32(const void* p) {
    uint32_t a;
    asm("{ .reg .u64 t; cvta.to.shared.u64 t, %1; cvt.u32.u64 %0, t; }"
        : "=r"(a) : "l"(p));
    return a;
}
__device__ __forceinline__ float tanh_fast(float x) {
    float y;
    asm("tanh.approx.f32 %0, %1;" : "=f"(y) : "f"(x));
    return y;
}
__device__ __forceinline__ float sig_fast(float x) {
    return fmaf(0.5f, tanh_fast(0.5f * x), 0.5f);
}
// pack two f32 -> f16x2 {lo, hi}
__device__ __forceinline__ uint32_t f16x2(float hi, float lo) {
    uint32_t r;
    asm("cvt.rn.f16x2.f32 %0, %1, %2;" : "=r"(r) : "f"(hi), "f"(lo));
    return r;
}
__device__ __forceinline__ void ldmatrix_x4(uint32_t& r0, uint32_t& r1,
                                            uint32_t& r2, uint32_t& r3,
                                            uint32_t addr) {
    asm volatile("ldmatrix.sync.aligned.m8n8.x4.shared.b16 {%0,%1,%2,%3}, [%4];"
                 : "=r"(r0), "=r"(r1), "=r"(r2), "=r"(r3) : "r"(addr));
}
__device__ __forceinline__ void ldmatrix_x2(uint32_t& r0, uint32_t& r1,
                                            uint32_t addr) {
    asm volatile("ldmatrix.sync.aligned.m8n8.x2.shared.b16 {%0,%1}, [%2];"
                 : "=r"(r0), "=r"(r1) : "r"(addr));
}
__device__ __forceinline__ void mma16816(float* d, uint32_t a0, uint32_t a1,
                                         uint32_t a2, uint32_t a3,
                                         uint32_t b0, uint32_t b1) {
    asm volatile(
        "mma.sync.aligned.m16n8k16.row.col.f32.f16.f16.f32 "
        "{%0,%1,%2,%3}, {%4,%5,%6,%7}, {%8,%9}, {%0,%1,%2,%3};"
        : "+f"(d[0]), "+f"(d[1]), "+f"(d[2]), "+f"(d[3])
        : "r"(a0), "r"(a1), "r"(a2), "r"(a3), "r"(b0), "r"(b1));
}
__device__ __forceinline__ void mma16808(float* d, uint32_t a0, uint32_t a1,
                                         uint32_t b0) {
    asm volatile(
        "mma.sync.aligned.m16n8k8.row.col.f32.f16.f16.f32 "
        "{%0,%1,%2,%3}, {%4,%5}, {%6}, {%0,%1,%2,%3};"
        : "+f"(d[0]), "+f"(d[1]), "+f"(d[2]), "+f"(d[3])
        : "r"(a0), "r"(a1), "r"(b0));
}
__device__ __forceinline__ uint32_t sw128(uint32_t off) {
    return off ^ ((off >> 3) & 0x70);
}

// ---------------------------------------------------------------------------
// Problem constants
// ---------------------------------------------------------------------------
#define B_    4
#define T_    32
#define H_    64
#define W_    64
#define COUT_ 64
#define HW_   4096

// K layout: pair p = j = ci*9+kh*3+kw (0..26), halves = kd {t-1, t}.
// Pair 27: A = {1.0, 0}, B = {bias, 0}. MMA covers pairs 0..23 (3 x k16) + 24..27 (k8).
// B row n: tile8=n>>3, jj=n&7 -> cout c=(tile8>>1)*4+(jj>>1), gate=(tile8&1)*2+(jj&1)
// CTA = 8x8 px tile, 256 threads / 8 warps; warp wid handles ALL 64 px x 32 n-rows
// (nq8 = wid). 2 CTAs co-resident per SM -> cross-CTA pipe overlap.

// SMEM layout (bytes)
#define SM_B_OFF    0                    // B fp16 [256 n][128 B]        = 32768
#define SM_A0_OFF   32768                // A fp16 buffer 0 (64 px)      = 8192
#define SM_A1_OFF   40960                // A fp16 buffer 1              = 8192
#define SM_HALO_OFF 49152                // halo 3 planes x 304 f32      = 3648
#define SM_TOTAL    52800
#define HPLANE      304

#define CT_ 256

__global__ void __launch_bounds__(CT_, 2)
fused_mma_kernel(const float* __restrict__ X,
                 const float* __restrict__ Wc, const float* __restrict__ bconv,
                 const float* __restrict__ Wci, const float* __restrict__ Wcf,
                 const float* __restrict__ Wco, float* __restrict__ out) {
    extern __shared__ __align__(1024) char sm[];
    const uint32_t smb = smem_u32(sm);
    float* hsm = (float*)(sm + SM_HALO_OFF);    // [plane = t mod 3][idx]

    const int tid  = threadIdx.x;
    const int wid  = tid >> 5;
    const int lane = tid & 31;
    const int nq8  = wid;                       // N-eighth: 32 gate rows
    const int tile = blockIdx.x;                // 0..63
    const int b    = blockIdx.y;                // 0..3
    const int trow = (tile >> 3) * 8;
    const int tcol = (tile & 7) * 8;

    const float* Xb = X + (size_t)b * 3 * T_ * HW_;

    // ---- prologue: B weights + bias (fp16, SW128), A const cols in BOTH bufs ----
    for (int i = tid; i < 256 * 32; i += CT_) {
        int n = i >> 5;
        int p = i & 31;
        int tile8 = n >> 3;
        int jj    = n & 7;
        int c     = (tile8 >> 1) * 4 + (jj >> 1);
        int gate  = (tile8 & 1) * 2 + (jj & 1);
        int o     = gate * 64 + c;
        float v0 = 0.f, v1 = 0.f;
        if (p < 27) {
            int ci  = p / 9;
            int khw = p - ci * 9;
            v0 = Wc[o * 54 + ci * 18 + khw];
            v1 = Wc[o * 54 + ci * 18 + 9 + khw];
        } else if (p == 27) {
            v0 = bconv[o];
        }
        *(uint32_t*)(sm + SM_B_OFF + sw128((uint32_t)(n * 128 + p * 4))) = f16x2(v1, v0);
    }
    for (int i = tid; i < 64 * 5; i += CT_) {
        int px = i / 5;
        int p  = 27 + (i - px * 5);
        uint32_t v = (p == 27) ? f16x2(0.f, 1.f) : 0u;
        uint32_t arel = sw128((uint32_t)(px * 128 + p * 4));
        *(uint32_t*)(sm + SM_A0_OFF + arel) = v;
        *(uint32_t*)(sm + SM_A1_OFF + arel) = v;
    }

    // ---- halo prefetch descriptors (t-invariant): 300 items, 10x10x3 ----
    int h0idx, h0goff; bool h0ok;
    {
        int i  = tid;                   // 0..255
        int ci = i / 100;
        int rem = i - ci * 100;
        int rr = rem / 10;
        int cc = rem - rr * 10;
        int hh = trow - 1 + rr;
        int ww = tcol - 1 + cc;
        h0ok   = (hh >= 0 && hh < H_ && ww >= 0 && ww < W_);
        h0idx  = i;
        h0goff = ci * (T_ * HW_) + hh * W_ + ww;
    }
    int h1idx = 0, h1goff = 0; bool h1ok = false;
    if (tid < 44) {
        int i  = tid + 256;             // 256..299
        int ci = i / 100;
        int rem = i - ci * 100;
        int rr = rem / 10;
        int cc = rem - rr * 10;
        int hh = trow - 1 + rr;
        int ww = tcol - 1 + cc;
        h1ok   = (hh >= 0 && hh < H_ && ww >= 0 && ww < W_);
        h1idx  = i;
        h1goff = ci * (T_ * HW_) + hh * W_ + ww;
    }
    // planes: 0 <- x(0), 1 <- x(1), 2 <- 0 (x(-1); (-1) mod 3 == 2)
    hsm[h0idx]              = h0ok ? Xb[h0goff] : 0.f;
    hsm[HPLANE + h0idx]     = h0ok ? Xb[h0goff + HW_] : 0.f;
    hsm[2 * HPLANE + h0idx] = 0.f;
    if (tid < 44) {
        hsm[h1idx]              = h1ok ? Xb[h1goff] : 0.f;
        hsm[HPLANE + h1idx]     = h1ok ? Xb[h1goff + HW_] : 0.f;
        hsm[2 * HPLANE + h1idx] = 0.f;
    }

    // ---- A-build descriptors packed: (swizzled A-rel offset << 10) | halo idx ----
    // 64 px x 27 pairs = 1728 items, 7 per thread
    uint32_t adesc[7];
#pragma unroll
    for (int k = 0; k < 7; k++) {
        int i = tid + k * CT_;
        if (i < 64 * 27) {
            int px = i / 27;
            int p  = i - px * 27;
            int ci  = p / 9;
            int khw = p - ci * 9;
            int kh  = khw / 3;
            int kw  = khw - kh * 3;
            uint32_t asoff = (uint32_t)(ci * 100 + ((px >> 3) + kh) * 10 + ((px & 7) + kw));
            uint32_t arel  = sw128((uint32_t)(px * 128 + p * 4));
            adesc[k] = (arel << 10) | asoff;
        } else {
            adesc[k] = 0xFFFFFFFFu;
        }
    }

    // ---- peephole params -> fp16 registers ----
    // cell m = mt*4 + gg*2 + rs: cout c = (nq8*2+gg)*4 + q,
    //   pixel (h,w) = (trow + mt*2 + rs, tcol + lr)
    const int q  = lane & 3;
    const int lr = lane >> 2;
    const int r8 = lane & 7;
    const int g  = lane >> 3;

    __half2 wifh[16];
    __half2 wcoh[8];
    {
        float wcot[16];
#pragma unroll
        for (int m = 0; m < 16; m++) {
            int mt = m >> 2;
            int gg = (m >> 1) & 1;
            int rs = m & 1;
            int c   = (nq8 * 2 + gg) * 4 + q;
            int hwm = (trow + mt * 2 + rs) * 64 + tcol + lr;
            wifh[m] = __floats2half2_rn(Wci[c * HW_ + hwm], Wcf[c * HW_ + hwm]);
            wcot[m] = Wco[c * HW_ + hwm];
        }
#pragma unroll
        for (int j = 0; j < 8; j++)
            wcoh[j] = __floats2half2_rn(wcot[2 * j], wcot[2 * j + 1]);
    }
    __syncthreads();    // halo planes + B smem staged

    // ---- preload B fragments to registers (t-invariant!) ----
    const uint32_t cL  = (uint32_t)r8 << 4;
    const uint32_t dkA = (uint32_t)(g >> 1) * 16;
    const uint32_t dkB = (uint32_t)(g & 1) * 16;
    uint32_t Bf[24];    // [gg][kc][4]
    uint32_t Bt[4];     // [gg][2]
#pragma unroll
    for (int gg = 0; gg < 2; gg++) {
        uint32_t bb = smb + SM_B_OFF
                    + (uint32_t)(nq8 * 32 + gg * 16 + r8 + 8 * (g >> 1)) * 128;
#pragma unroll
        for (int kc = 0; kc < 3; kc++)
            ldmatrix_x4(Bf[gg*12+kc*4], Bf[gg*12+kc*4+1],
                        Bf[gg*12+kc*4+2], Bf[gg*12+kc*4+3],
                        bb + ((((uint32_t)kc * 32) + dkB) ^ cL));
        uint32_t bt = smb + SM_B_OFF
                    + (uint32_t)(nq8 * 32 + gg * 16 + (lane & 15)) * 128 + (96u ^ cL);
        ldmatrix_x2(Bt[gg*2], Bt[gg*2+1], bt);
    }

    // ---- prologue A-build(0) into buf 0: v0 = x(-1) (plane 2), v1 = x(0) ----
#pragma unroll
    for (int k = 0; k < 7; k++) {
        uint32_t d = adesc[k];
        if (d != 0xFFFFFFFFu) {
            uint32_t off = d & 1023;
            float v0 = hsm[2 * HPLANE + off];
            float v1 = hsm[off];
            *(uint32_t*)(sm + SM_A0_OFF + (d >> 10)) = f16x2(v1, v0);
        }
    }

    // ---- A ldmatrix lane-constant offsets (buf-relative) ----
    const uint32_t aRow4   = (uint32_t)(r8 + 8 * (g & 1)) * 128;
    const uint32_t tailRow = (uint32_t)(lane & 15) * 128 + (96u ^ cL);

    // ---- output base ----
    float* outb = out + ((size_t)(b * COUT_ + nq8 * 8 + q)) * (T_ * HW_)
                + trow * 64 + tcol + lr;
    const size_t ggstride = (size_t)4 * (T_ * HW_);   // cout += 4 per gg

    float C[16];
#pragma unroll
    for (int m = 0; m < 16; m++) C[m] = 0.f;

    float pf0 = 0.f, pf1 = 0.f;

    for (int t = 0; t < T_; t++) {
        __syncthreads();   // A(t) built; halo plane (t+1)%3 stored; prior reads done

        const int pl0 = t % 3;              // x(t)
        const int pl1 = (t + 1) % 3;        // x(t+1)
        const int pl2 = (t + 2) % 3;        // store target for prefetch

        // ---- prefetch halo plane t+2 (LDG; stored at end of iter) ----
        if (t + 2 < T_) {
            const int toff = (t + 2) * HW_;
            pf0 = h0ok ? Xb[h0goff + toff] : 0.f;
            if (tid < 44) pf1 = h1ok ? Xb[h1goff + toff] : 0.f;
        }

        // ---- A-build(t+1) into buf[(t+1)&1] — overlaps MMA below ----
        if (t + 1 < T_) {
            char* ab = sm + SM_A0_OFF + (size_t)((t + 1) & 1) * 8192;
            const float* hb0 = hsm + pl0 * HPLANE;
            const float* hb1 = hsm + pl1 * HPLANE;
#pragma unroll
            for (int k = 0; k < 7; k++) {
                uint32_t d = adesc[k];
                if (d != 0xFFFFFFFFu) {
                    uint32_t off = d & 1023;
                    float v0 = hb0[off];    // x(t)   (kd=0 for step t+1)
                    float v1 = hb1[off];    // x(t+1) (kd=1)
                    *(uint32_t*)(ab + (d >> 10)) = f16x2(v1, v0);
                }
            }
        }

        // ---- per M16-tile: stream A, MMA vs reg-resident B, recurrence ----
        const uint32_t abuf = smb + (uint32_t)SM_A0_OFF + (uint32_t)(t & 1) * 8192;
        const size_t tof = (size_t)t * HW_;

#pragma unroll
        for (int mt = 0; mt < 4; mt++) {
            float acc[16];
#pragma unroll
            for (int m = 0; m < 16; m++) acc[m] = 0.f;

            const uint32_t aT = abuf + aRow4 + (uint32_t)mt * 2048;
#pragma unroll
            for (int kc = 0; kc < 3; kc++) {
                uint32_t a0, a1, a2, a3;
                ldmatrix_x4(a0, a1, a2, a3, aT + ((((uint32_t)kc * 32) + dkA) ^ cL));
                mma16816(acc,      a0, a1, a2, a3, Bf[kc*4],      Bf[kc*4+1]);
                mma16816(acc + 4,  a0, a1, a2, a3, Bf[kc*4+2],    Bf[kc*4+3]);
                mma16816(acc + 8,  a0, a1, a2, a3, Bf[12+kc*4],   Bf[12+kc*4+1]);
                mma16816(acc + 12, a0, a1, a2, a3, Bf[12+kc*4+2], Bf[12+kc*4+3]);
            }
            {   // k8 tail: pairs 24..27 (incl. bias)
                uint32_t at0, at1;
                ldmatrix_x2(at0, at1, abuf + tailRow + (uint32_t)mt * 2048);
                mma16808(acc,      at0, at1, Bt[0]);
                mma16808(acc + 4,  at0, at1, Bt[1]);
                mma16808(acc + 8,  at0, at1, Bt[2]);
                mma16808(acc + 12, at0, at1, Bt[3]);
            }

            // recurrence: 4 cells = 2 cout-groups x 2 pixel rows
            float* opt = outb + tof + (size_t)(mt * 2) * 64;
#pragma unroll
            for (int gg = 0; gg < 2; gg++) {
                const float* A = acc + gg * 8;   // [i0 f0 i1 f1 | g0 o0 g1 o1]
#pragma unroll
                for (int rs = 0; rs < 2; rs++) {
                    const int m = mt * 4 + gg * 2 + rs;
                    float iv = A[rs * 2];
                    float fv = A[rs * 2 + 1];
                    float gv = A[4 + rs * 2];
                    float ov = A[5 + rs * 2];
                    float2 wif = __half22float2(wifh[m]);
                    float wco  = rs ? __high2float(wcoh[m >> 1])
                                    : __low2float(wcoh[m >> 1]);
                    float Cp = C[m];
                    float ig = sig_fast(iv + wif.x * Cp);
                    float fg = sig_fast(fv + wif.y * Cp);
                    float Cn = fg * Cp + ig * tanh_fast(gv);
                    float og = sig_fast(ov + wco * Cn);
                    opt[gg * ggstride + (size_t)rs * 64] = og * tanh_fast(Cn);
                    C[m] = Cn;
                }
            }
        }

        // ---- store prefetched halo(t+2) into plane pl2 (retired plane) ----
        if (t + 2 < T_) {
            hsm[pl2 * HPLANE + h0idx] = pf0;
            if (tid < 44) hsm[pl2 * HPLANE + h1idx] = pf1;
        }
    }
}

// ---------------------------------------------------------------------------
// kernel_launch
// ---------------------------------------------------------------------------
extern "C" void kernel_launch(void* const* d_in, const int* in_sizes, int n_in,
                              void* d_out, int out_size) {
    const float* X     = (const float*)d_in[0];
    const float* Wc    = (const float*)d_in[1];
    const float* bconv = (const float*)d_in[2];
    const float* Wci   = (const float*)d_in[3];
    const float* Wcf   = (const float*)d_in[4];
    const float* Wco   = (const float*)d_in[5];
    float* out = (float*)d_out;

    cudaFuncSetAttribute(fused_mma_kernel, cudaFuncAttributeMaxDynamicSharedMemorySize,
                         SM_TOTAL);

    dim3 grid(64, B_);   // 64 tiles x 4 batches = 256 CTAs (2 per SM, 1 wave)
    fused_mma_kernel<<<grid, CT_, SM_TOTAL>>>(X, Wc, bconv, Wci, Wcf, Wco, out);
}